// round 3
// baseline (speedup 1.0000x reference)
#include <cuda_runtime.h>
#include <cstdint>

#define N_NODES 100000
#define N_EDGES 1250000
#define FEAT    64     // IN_FEATS == N_HIDDEN == 64
#define NCLS    32

// ---- scratch (no allocations allowed; __device__ globals) ----
__device__ __align__(16) float g_deg[N_NODES];
__device__ __align__(16) float g_agg[(size_t)N_NODES * FEAT];
__device__ __align__(16) float g_h1 [(size_t)N_NODES * FEAT];

// ---------------------------------------------------------------------------
// zero agg (and deg on first pass)
// ---------------------------------------------------------------------------
__global__ void zero_kernel(int zero_deg) {
    int i = blockIdx.x * blockDim.x + threadIdx.x;
    const int tot4 = N_NODES * FEAT / 4;
    if (i < tot4)
        reinterpret_cast<float4*>(g_agg)[i] = make_float4(0.f, 0.f, 0.f, 0.f);
    if (zero_deg && i < N_NODES)
        g_deg[i] = 0.f;
}

// ---------------------------------------------------------------------------
// degree count
// ---------------------------------------------------------------------------
__global__ void deg_kernel(const int* __restrict__ dst) {
    int e = blockIdx.x * blockDim.x + threadIdx.x;
    if (e < N_EDGES)
        atomicAdd(&g_deg[__ldg(&dst[e])], 1.0f);
}

// ---------------------------------------------------------------------------
// scatter: agg[dst] += feat[src]   (16 threads per edge, float4 chunks,
// vector atomicAdd(float4*) -> RED.E.ADD.F32X4 — 1 L2 op per 16B)
// use_h1: 0 -> feat = x (kernel arg), 1 -> feat = g_h1
// ---------------------------------------------------------------------------
__global__ void scatter_kernel(const float* __restrict__ x,
                               const int* __restrict__ src,
                               const int* __restrict__ dst,
                               int use_h1) {
    long long t = (long long)blockIdx.x * blockDim.x + threadIdx.x;
    if (t >= (long long)N_EDGES * 16) return;
    int e = (int)(t >> 4);
    int c = ((int)t & 15) * 4;

    const float* feat = use_h1 ? g_h1 : x;
    int s = __ldg(&src[e]);
    int d = __ldg(&dst[e]);

    float4 v = *reinterpret_cast<const float4*>(feat + (size_t)s * FEAT + c);
    float4* p = reinterpret_cast<float4*>(g_agg + (size_t)d * FEAT + c);
#if __CUDA_ARCH__ >= 900
    atomicAdd(p, v);
#else
    atomicAdd(&p->x, v.x); atomicAdd(&p->y, v.y);
    atomicAdd(&p->z, v.z); atomicAdd(&p->w, v.w);
#endif
}

// ---------------------------------------------------------------------------
// dense layer 1: h1 = relu(x @ Ws + (agg/max(deg,1)) @ Wn + b)
// thread-per-node; W in shared (warp-uniform broadcast loads)
// ---------------------------------------------------------------------------
__global__ void dense1_kernel(const float* __restrict__ x,
                              const float* __restrict__ Ws,
                              const float* __restrict__ Wn,
                              const float* __restrict__ b) {
    __shared__ float sWs[FEAT * FEAT];
    __shared__ float sWn[FEAT * FEAT];
    __shared__ float sb[FEAT];
    for (int i = threadIdx.x; i < FEAT * FEAT; i += blockDim.x) {
        sWs[i] = Ws[i];
        sWn[i] = Wn[i];
    }
    for (int i = threadIdx.x; i < FEAT; i += blockDim.x) sb[i] = b[i];
    __syncthreads();

    int n = blockIdx.x * blockDim.x + threadIdx.x;
    if (n >= N_NODES) return;

    float invd = 1.0f / fmaxf(g_deg[n], 1.0f);

    float4 acc[FEAT / 4];
#pragma unroll
    for (int o4 = 0; o4 < FEAT / 4; o4++)
        acc[o4] = reinterpret_cast<const float4*>(sb)[o4];

    const float4* xr = reinterpret_cast<const float4*>(x + (size_t)n * FEAT);
    const float4* ar = reinterpret_cast<const float4*>(g_agg + (size_t)n * FEAT);

    for (int kc = 0; kc < FEAT / 4; kc++) {
        float4 xv = xr[kc];
        float4 av = ar[kc];
        float xs[4] = {xv.x, xv.y, xv.z, xv.w};
        float hs[4] = {av.x * invd, av.y * invd, av.z * invd, av.w * invd};
        int kbase = kc * 4;
#pragma unroll
        for (int kk = 0; kk < 4; kk++) {
            const float4* ws = reinterpret_cast<const float4*>(sWs + (kbase + kk) * FEAT);
            const float4* wn = reinterpret_cast<const float4*>(sWn + (kbase + kk) * FEAT);
            float a = xs[kk], h = hs[kk];
#pragma unroll
            for (int o4 = 0; o4 < FEAT / 4; o4++) {
                float4 w1 = ws[o4];
                float4 w2 = wn[o4];
                acc[o4].x += a * w1.x + h * w2.x;
                acc[o4].y += a * w1.y + h * w2.y;
                acc[o4].z += a * w1.z + h * w2.z;
                acc[o4].w += a * w1.w + h * w2.w;
            }
        }
    }

    float4* out = reinterpret_cast<float4*>(g_h1 + (size_t)n * FEAT);
#pragma unroll
    for (int o4 = 0; o4 < FEAT / 4; o4++) {
        float4 v = acc[o4];
        v.x = fmaxf(v.x, 0.f); v.y = fmaxf(v.y, 0.f);
        v.z = fmaxf(v.z, 0.f); v.w = fmaxf(v.w, 0.f);
        out[o4] = v;
    }
}

// ---------------------------------------------------------------------------
// dense layer 2: out = h1 @ Ws2 + (agg/max(deg,1)) @ Wn2 + b2   (32 outputs)
// ---------------------------------------------------------------------------
__global__ void dense2_kernel(const float* __restrict__ Ws,
                              const float* __restrict__ Wn,
                              const float* __restrict__ b,
                              float* __restrict__ out) {
    __shared__ float sWs[FEAT * NCLS];
    __shared__ float sWn[FEAT * NCLS];
    __shared__ float sb[NCLS];
    for (int i = threadIdx.x; i < FEAT * NCLS; i += blockDim.x) {
        sWs[i] = Ws[i];
        sWn[i] = Wn[i];
    }
    for (int i = threadIdx.x; i < NCLS; i += blockDim.x) sb[i] = b[i];
    __syncthreads();

    int n = blockIdx.x * blockDim.x + threadIdx.x;
    if (n >= N_NODES) return;

    float invd = 1.0f / fmaxf(g_deg[n], 1.0f);

    float4 acc[NCLS / 4];
#pragma unroll
    for (int o4 = 0; o4 < NCLS / 4; o4++)
        acc[o4] = reinterpret_cast<const float4*>(sb)[o4];

    const float4* xr = reinterpret_cast<const float4*>(g_h1 + (size_t)n * FEAT);
    const float4* ar = reinterpret_cast<const float4*>(g_agg + (size_t)n * FEAT);

    for (int kc = 0; kc < FEAT / 4; kc++) {
        float4 xv = xr[kc];
        float4 av = ar[kc];
        float xs[4] = {xv.x, xv.y, xv.z, xv.w};
        float hs[4] = {av.x * invd, av.y * invd, av.z * invd, av.w * invd};
        int kbase = kc * 4;
#pragma unroll
        for (int kk = 0; kk < 4; kk++) {
            const float4* ws = reinterpret_cast<const float4*>(sWs + (kbase + kk) * NCLS);
            const float4* wn = reinterpret_cast<const float4*>(sWn + (kbase + kk) * NCLS);
            float a = xs[kk], h = hs[kk];
#pragma unroll
            for (int o4 = 0; o4 < NCLS / 4; o4++) {
                float4 w1 = ws[o4];
                float4 w2 = wn[o4];
                acc[o4].x += a * w1.x + h * w2.x;
                acc[o4].y += a * w1.y + h * w2.y;
                acc[o4].z += a * w1.z + h * w2.z;
                acc[o4].w += a * w1.w + h * w2.w;
            }
        }
    }

    float4* op = reinterpret_cast<float4*>(out + (size_t)n * NCLS);
#pragma unroll
    for (int o4 = 0; o4 < NCLS / 4; o4++)
        op[o4] = acc[o4];
}

// ---------------------------------------------------------------------------
extern "C" void kernel_launch(void* const* d_in, const int* in_sizes, int n_in,
                              void* d_out, int out_size) {
    const float* x   = (const float*)d_in[0];
    const int*   src = (const int*)d_in[1];
    const int*   dst = (const int*)d_in[2];
    const float* Ws1 = (const float*)d_in[3];
    const float* Wn1 = (const float*)d_in[4];
    const float* b1  = (const float*)d_in[5];
    const float* Ws2 = (const float*)d_in[6];
    const float* Wn2 = (const float*)d_in[7];
    const float* b2  = (const float*)d_in[8];
    float* out = (float*)d_out;

    const int ZT = 256;
    int zero_n = N_NODES * FEAT / 4;          // covers both agg (v4) and deg
    int zero_blocks = (zero_n + ZT - 1) / ZT;

    const int ET = 256;
    int deg_blocks = (N_EDGES + ET - 1) / ET;
    long long sc_threads = (long long)N_EDGES * 16;
    int sc_blocks = (int)((sc_threads + ET - 1) / ET);

    const int DT = 128;
    int dn_blocks = (N_NODES + DT - 1) / DT;

    // layer 1
    zero_kernel<<<zero_blocks, ZT>>>(1);
    deg_kernel<<<deg_blocks, ET>>>(dst);
    scatter_kernel<<<sc_blocks, ET>>>(x, src, dst, 0);
    dense1_kernel<<<dn_blocks, DT>>>(x, Ws1, Wn1, b1);

    // layer 2
    zero_kernel<<<zero_blocks, ZT>>>(0);
    scatter_kernel<<<sc_blocks, ET>>>(x, src, dst, 1);
    dense2_kernel<<<dn_blocks, DT>>>(Ws2, Wn2, b2, out);
}

// round 4
// speedup vs baseline: 1.0677x; 1.0677x over previous
#include <cuda_runtime.h>
#include <cstdint>

#define N_NODES 100000
#define N_EDGES 1250000
#define FEAT    64     // IN_FEATS == N_HIDDEN == 64
#define NCLS    32

// ---- scratch (no allocations allowed; __device__ globals) ----
__device__ __align__(16) float g_deg[N_NODES];
__device__ __align__(16) float g_agg[(size_t)N_NODES * FEAT];   // reused: 64 cols L1, 32 cols L2
__device__ __align__(16) float g_h1 [(size_t)N_NODES * FEAT];
__device__ __align__(16) float g_t  [(size_t)N_NODES * NCLS];   // h1 @ Wn2

// ---------------------------------------------------------------------------
// zero agg (64 cols) + deg
// ---------------------------------------------------------------------------
__global__ void zero1_kernel() {
    int i = blockIdx.x * blockDim.x + threadIdx.x;
    const int tot4 = N_NODES * FEAT / 4;
    if (i < tot4)
        reinterpret_cast<float4*>(g_agg)[i] = make_float4(0.f, 0.f, 0.f, 0.f);
    if (i < N_NODES)
        g_deg[i] = 0.f;
}

// zero agg (32 cols, row stride NCLS)
__global__ void zero2_kernel() {
    int i = blockIdx.x * blockDim.x + threadIdx.x;
    const int tot4 = N_NODES * NCLS / 4;
    if (i < tot4)
        reinterpret_cast<float4*>(g_agg)[i] = make_float4(0.f, 0.f, 0.f, 0.f);
}

// ---------------------------------------------------------------------------
// scatter layer 1: agg[dst] += x[src]  (16 threads/edge, F32X4 vector RED)
// lane c==0 also counts degree.
// ---------------------------------------------------------------------------
__global__ void scatter1_kernel(const float* __restrict__ x,
                                const int* __restrict__ src,
                                const int* __restrict__ dst) {
    long long t = (long long)blockIdx.x * blockDim.x + threadIdx.x;
    if (t >= (long long)N_EDGES * 16) return;
    int e = (int)(t >> 4);
    int c = ((int)t & 15);

    int s = __ldg(&src[e]);
    int d = __ldg(&dst[e]);

    float4 v = *reinterpret_cast<const float4*>(x + (size_t)s * FEAT + c * 4);
    float4* p = reinterpret_cast<float4*>(g_agg + (size_t)d * FEAT + c * 4);
    atomicAdd(p, v);
    if (c == 0)
        atomicAdd(&g_deg[d], 1.0f);
}

// ---------------------------------------------------------------------------
// scatter layer 2: agg32[dst] += t[src]  (8 threads/edge)
// ---------------------------------------------------------------------------
__global__ void scatter2_kernel(const int* __restrict__ src,
                                const int* __restrict__ dst) {
    long long t = (long long)blockIdx.x * blockDim.x + threadIdx.x;
    if (t >= (long long)N_EDGES * 8) return;
    int e = (int)(t >> 3);
    int c = ((int)t & 7);

    int s = __ldg(&src[e]);
    int d = __ldg(&dst[e]);

    float4 v = *reinterpret_cast<const float4*>(g_t + (size_t)s * NCLS + c * 4);
    float4* p = reinterpret_cast<float4*>(g_agg + (size_t)d * NCLS + c * 4);
    atomicAdd(p, v);
}

// ---------------------------------------------------------------------------
// dense layer 1: h1 = relu(x @ Ws + (agg/max(deg,1)) @ Wn + b)
// 256 threads/block, 128 nodes/block. Each warp handles 32 nodes × 32 outputs;
// warp&1 selects output half (warp-uniform -> broadcast LDS for weights).
// ---------------------------------------------------------------------------
__global__ void __launch_bounds__(256, 4)
dense1_kernel(const float* __restrict__ x,
              const float* __restrict__ Ws,
              const float* __restrict__ Wn,
              const float* __restrict__ b) {
    __shared__ float sWs[FEAT * FEAT];
    __shared__ float sWn[FEAT * FEAT];
    __shared__ float sb[FEAT];
    for (int i = threadIdx.x; i < FEAT * FEAT; i += blockDim.x) {
        sWs[i] = Ws[i];
        sWn[i] = Wn[i];
    }
    if (threadIdx.x < FEAT) sb[threadIdx.x] = b[threadIdx.x];
    __syncthreads();

    int warp = threadIdx.x >> 5, lane = threadIdx.x & 31;
    int half = warp & 1;                    // warp-uniform output half
    int ob = half * 32;                     // output base
    int n = blockIdx.x * 128 + (warp >> 1) * 32 + lane;
    if (n >= N_NODES) return;

    float invd = 1.0f / fmaxf(g_deg[n], 1.0f);

    float4 acc[8];
#pragma unroll
    for (int j = 0; j < 8; j++)
        acc[j] = reinterpret_cast<const float4*>(sb + ob)[j];

    const float4* xr = reinterpret_cast<const float4*>(x + (size_t)n * FEAT);
    const float4* ar = reinterpret_cast<const float4*>(g_agg + (size_t)n * FEAT);

    for (int kc = 0; kc < FEAT / 4; kc++) {
        float4 xv = xr[kc];
        float4 av = ar[kc];
        float xs[4] = {xv.x, xv.y, xv.z, xv.w};
        float hs[4] = {av.x * invd, av.y * invd, av.z * invd, av.w * invd};
        int kbase = kc * 4;
#pragma unroll
        for (int kk = 0; kk < 4; kk++) {
            const float4* ws = reinterpret_cast<const float4*>(sWs + (kbase + kk) * FEAT + ob);
            const float4* wn = reinterpret_cast<const float4*>(sWn + (kbase + kk) * FEAT + ob);
            float a = xs[kk], h = hs[kk];
#pragma unroll
            for (int j = 0; j < 8; j++) {
                float4 w1 = ws[j];
                float4 w2 = wn[j];
                acc[j].x += a * w1.x + h * w2.x;
                acc[j].y += a * w1.y + h * w2.y;
                acc[j].z += a * w1.z + h * w2.z;
                acc[j].w += a * w1.w + h * w2.w;
            }
        }
    }

    float4* out = reinterpret_cast<float4*>(g_h1 + (size_t)n * FEAT + ob);
#pragma unroll
    for (int j = 0; j < 8; j++) {
        float4 v = acc[j];
        v.x = fmaxf(v.x, 0.f); v.y = fmaxf(v.y, 0.f);
        v.z = fmaxf(v.z, 0.f); v.w = fmaxf(v.w, 0.f);
        out[j] = v;
    }
}

// ---------------------------------------------------------------------------
// transform for layer 2:
//   half 0 warps: out[n]  = h1[n] @ Ws2 + b2   (partial output, 32 vals)
//   half 1 warps: g_t[n]  = h1[n] @ Wn2        (to be scattered, 32 vals)
// 256 threads/block, 128 nodes/block.
// ---------------------------------------------------------------------------
__global__ void __launch_bounds__(256, 4)
trans2_kernel(const float* __restrict__ Ws,
              const float* __restrict__ Wn,
              const float* __restrict__ b,
              float* __restrict__ out) {
    __shared__ float sWs[FEAT * NCLS];
    __shared__ float sWn[FEAT * NCLS];
    __shared__ float sb[NCLS];
    for (int i = threadIdx.x; i < FEAT * NCLS; i += blockDim.x) {
        sWs[i] = Ws[i];
        sWn[i] = Wn[i];
    }
    if (threadIdx.x < NCLS) sb[threadIdx.x] = b[threadIdx.x];
    __syncthreads();

    int warp = threadIdx.x >> 5, lane = threadIdx.x & 31;
    int half = warp & 1;                    // 0 -> self path, 1 -> neigh path
    int n = blockIdx.x * 128 + (warp >> 1) * 32 + lane;
    if (n >= N_NODES) return;

    const float* sW = half ? sWn : sWs;

    float4 acc[8];
#pragma unroll
    for (int j = 0; j < 8; j++)
        acc[j] = half ? make_float4(0.f, 0.f, 0.f, 0.f)
                      : reinterpret_cast<const float4*>(sb)[j];

    const float4* xr = reinterpret_cast<const float4*>(g_h1 + (size_t)n * FEAT);

    for (int kc = 0; kc < FEAT / 4; kc++) {
        float4 xv = xr[kc];
        float xs[4] = {xv.x, xv.y, xv.z, xv.w};
        int kbase = kc * 4;
#pragma unroll
        for (int kk = 0; kk < 4; kk++) {
            const float4* w = reinterpret_cast<const float4*>(sW + (kbase + kk) * NCLS);
            float a = xs[kk];
#pragma unroll
            for (int j = 0; j < 8; j++) {
                float4 wv = w[j];
                acc[j].x += a * wv.x;
                acc[j].y += a * wv.y;
                acc[j].z += a * wv.z;
                acc[j].w += a * wv.w;
            }
        }
    }

    float* dstp = half ? (g_t + (size_t)n * NCLS) : (out + (size_t)n * NCLS);
    float4* dp = reinterpret_cast<float4*>(dstp);
#pragma unroll
    for (int j = 0; j < 8; j++)
        dp[j] = acc[j];
}

// ---------------------------------------------------------------------------
// finalize: out[n][:] += agg32[n][:] / max(deg,1)
// ---------------------------------------------------------------------------
__global__ void finalize_kernel(float* __restrict__ out) {
    int i = blockIdx.x * blockDim.x + threadIdx.x;
    const int tot4 = N_NODES * NCLS / 4;
    if (i >= tot4) return;
    int n = i >> 3;                          // 8 float4 per node
    float invd = 1.0f / fmaxf(g_deg[n], 1.0f);
    float4 a = reinterpret_cast<const float4*>(g_agg)[i];
    float4* o = reinterpret_cast<float4*>(out) + i;
    float4 v = *o;
    v.x += a.x * invd; v.y += a.y * invd;
    v.z += a.z * invd; v.w += a.w * invd;
    *o = v;
}

// ---------------------------------------------------------------------------
extern "C" void kernel_launch(void* const* d_in, const int* in_sizes, int n_in,
                              void* d_out, int out_size) {
    const float* x   = (const float*)d_in[0];
    const int*   src = (const int*)d_in[1];
    const int*   dst = (const int*)d_in[2];
    const float* Ws1 = (const float*)d_in[3];
    const float* Wn1 = (const float*)d_in[4];
    const float* b1  = (const float*)d_in[5];
    const float* Ws2 = (const float*)d_in[6];
    const float* Wn2 = (const float*)d_in[7];
    const float* b2  = (const float*)d_in[8];
    float* out = (float*)d_out;

    const int T = 256;
    int z1_blocks = (N_NODES * FEAT / 4 + T - 1) / T;
    int z2_blocks = (N_NODES * NCLS / 4 + T - 1) / T;

    long long s1_threads = (long long)N_EDGES * 16;
    int s1_blocks = (int)((s1_threads + T - 1) / T);
    long long s2_threads = (long long)N_EDGES * 8;
    int s2_blocks = (int)((s2_threads + T - 1) / T);

    int dn_blocks = (N_NODES + 127) / 128;   // 256 thr, 128 nodes per block
    int fin_blocks = (N_NODES * NCLS / 4 + T - 1) / T;

    // layer 1
    zero1_kernel<<<z1_blocks, T>>>();
    scatter1_kernel<<<s1_blocks, T>>>(x, src, dst);
    dense1_kernel<<<dn_blocks, T>>>(x, Ws1, Wn1, b1);

    // layer 2 (agg(h1) @ Wn2 == agg(h1 @ Wn2): transform first, scatter 32 feats)
    trans2_kernel<<<dn_blocks, T>>>(Ws2, Wn2, b2, out);
    zero2_kernel<<<z2_blocks, T>>>();
    scatter2_kernel<<<s2_blocks, T>>>(src, dst);
    finalize_kernel<<<fin_blocks, T>>>(out);
}